// round 10
// baseline (speedup 1.0000x reference)
#include <cuda_runtime.h>
#include <cuda_bf16.h>
#include <math.h>
#include <stdint.h>

#define SQ   2048
#define D    1024
#define NH   16
#define DK   64
#define DFF  4096

// ================= PTX helpers (baseline ISA only) ==========================
__device__ __forceinline__ uint32_t smem_u32(const void* p) {
    uint32_t a;
    asm("{ .reg .u64 t; cvta.to.shared.u64 t, %1; cvt.u32.u64 %0, t; }" : "=r"(a) : "l"(p));
    return a;
}
__device__ __forceinline__ void cpa16(uint32_t dst, const void* src) {
    asm volatile("cp.async.cg.shared.global [%0], [%1], 16;" :: "r"(dst), "l"(src));
}
#define CPA_COMMIT() asm volatile("cp.async.commit_group;" ::: "memory")
__device__ __forceinline__ void ldm_x4(uint32_t& r0, uint32_t& r1, uint32_t& r2, uint32_t& r3, uint32_t addr) {
    asm volatile("ldmatrix.sync.aligned.m8n8.x4.shared.b16 {%0,%1,%2,%3}, [%4];"
                 : "=r"(r0), "=r"(r1), "=r"(r2), "=r"(r3) : "r"(addr));
}
__device__ __forceinline__ void ldm_x2(uint32_t& r0, uint32_t& r1, uint32_t addr) {
    asm volatile("ldmatrix.sync.aligned.m8n8.x2.shared.b16 {%0,%1}, [%2];"
                 : "=r"(r0), "=r"(r1) : "r"(addr));
}
__device__ __forceinline__ void ldm_x2t(uint32_t& r0, uint32_t& r1, uint32_t addr) {
    asm volatile("ldmatrix.sync.aligned.m8n8.x2.trans.shared.b16 {%0,%1}, [%2];"
                 : "=r"(r0), "=r"(r1) : "r"(addr));
}
__device__ __forceinline__ void mma_bf16(float* c, uint32_t a0, uint32_t a1, uint32_t a2, uint32_t a3,
                                         uint32_t b0, uint32_t b1) {
    asm volatile("mma.sync.aligned.m16n8k16.row.col.f32.bf16.bf16.f32 "
                 "{%0,%1,%2,%3}, {%4,%5,%6,%7}, {%8,%9}, {%0,%1,%2,%3};"
                 : "+f"(c[0]), "+f"(c[1]), "+f"(c[2]), "+f"(c[3])
                 : "r"(a0), "r"(a1), "r"(a2), "r"(a3), "r"(b0), "r"(b1));
}
__device__ __forceinline__ float wred_max(float v) {
#pragma unroll
    for (int o = 16; o > 0; o >>= 1) v = fmaxf(v, __shfl_xor_sync(0xffffffffu, v, o));
    return v;
}
__device__ __forceinline__ float wred_sum(float v) {
#pragma unroll
    for (int o = 16; o > 0; o >>= 1) v += __shfl_xor_sync(0xffffffffu, v, o);
    return v;
}

// ================= scratch =================
__device__ __nv_bfloat16 g_nx_h[SQ * D],  g_nx_l[SQ * D];
__device__ __nv_bfloat16 g_h_h[SQ * D],   g_h_l[SQ * D];
__device__ __nv_bfloat16 g_qkv_h[SQ * 3 * D], g_qkv_l[SQ * 3 * D];
__device__ __nv_bfloat16 g_ctx_h[SQ * D], g_ctx_l[SQ * D];
__device__ float         g_p1[SQ * D];
__device__ float         g_n2[SQ * D];
__device__ __nv_bfloat16 g_n2_h[SQ * D],  g_n2_l[SQ * D];
__device__ __nv_bfloat16 g_ff1_h[SQ * DFF], g_ff1_l[SQ * DFF];
__device__ float         g_attn_scratch[(size_t)NH * SQ * SQ];
__device__ __nv_bfloat16 g_attn_h[(size_t)NH * SQ * SQ];
__device__ __nv_bfloat16 g_attn_l[(size_t)NH * SQ * SQ];
// transposed/split weights [N, K]
__device__ __nv_bfloat16 g_wint_h[D * D],      g_wint_l[D * D];
__device__ __nv_bfloat16 g_wqkvt_h[3 * D * D], g_wqkvt_l[3 * D * D];
__device__ __nv_bfloat16 g_w2t_h[D * D],       g_w2t_l[D * D];
__device__ __nv_bfloat16 g_wf1t_h[DFF * D],    g_wf1t_l[DFF * D];
__device__ __nv_bfloat16 g_wf2t_h[D * DFF],    g_wf2t_l[D * DFF];
// WoW2 fold
__device__ __nv_bfloat16 g_wo_nt_h[D * D],     g_wo_nt_l[D * D];   // Wo straight split
__device__ __nv_bfloat16 g_comb_h[D * D],      g_comb_l[D * D];    // (Wo@W2)^T-as-B split
__device__ float         g_bcomb[D];
__device__ float         g_zero[D];   // zero-initialized, never written
__device__ float         g_bqkv[3 * D];

// ================= batched weight prep ======================================
__device__ __forceinline__ void wprep_tile(
    const float* __restrict__ W, __nv_bfloat16* __restrict__ Th,
    __nv_bfloat16* __restrict__ Tl, int K, int N, int rowoff, int n0, int k0)
{
    __shared__ float t[32][33];
    const int tx = threadIdx.x, ty = threadIdx.y;
    for (int i = ty; i < 32; i += 8)
        t[i][tx] = W[(size_t)(k0 + i) * N + n0 + tx];
    __syncthreads();
    for (int i = ty; i < 32; i += 8) {
        float v = t[tx][i];
        __nv_bfloat16 h = __float2bfloat16_rn(v);
        size_t o = (size_t)(rowoff + n0 + i) * K + k0 + tx;
        Th[o] = h;
        Tl[o] = __float2bfloat16_rn(v - __bfloat162float(h));
    }
}

// z = 0..5: transpose+split DxD; z = 6: straight split of Wo. Also concats qkv bias.
__global__ __launch_bounds__(256) void wprep_dd(
    const float* __restrict__ W_in, const float* __restrict__ Wq,
    const float* __restrict__ Wk,   const float* __restrict__ Wv,
    const float* __restrict__ Wo,   const float* __restrict__ W2,
    const float* __restrict__ bq,   const float* __restrict__ bk,
    const float* __restrict__ bv,
    __nv_bfloat16* winth, __nv_bfloat16* wintl,
    __nv_bfloat16* wqkvth, __nv_bfloat16* wqkvtl,
    __nv_bfloat16* wonth, __nv_bfloat16* wontl,
    __nv_bfloat16* w2th, __nv_bfloat16* w2tl, float* bqkv)
{
    const int z = blockIdx.z;
    if (z == 6) {
        // straight split of Wo [D, D] (row-major, no transpose)
        const int col = blockIdx.x * 32 + threadIdx.x;
        for (int i = threadIdx.y; i < 32; i += 8) {
            const int row = blockIdx.y * 32 + i;
            float v = Wo[(size_t)row * D + col];
            __nv_bfloat16 h = __float2bfloat16_rn(v);
            size_t o = (size_t)row * D + col;
            wonth[o] = h;
            wontl[o] = __float2bfloat16_rn(v - __bfloat162float(h));
        }
        return;
    }
    const float* W; __nv_bfloat16 *Th, *Tl; int rowoff = 0;
    switch (z) {
        case 0:  W = W_in; Th = winth;  Tl = wintl;  break;
        case 1:  W = Wq;   Th = wqkvth; Tl = wqkvtl; rowoff = 0;     break;
        case 2:  W = Wk;   Th = wqkvth; Tl = wqkvtl; rowoff = D;     break;
        case 3:  W = Wv;   Th = wqkvth; Tl = wqkvtl; rowoff = 2 * D; break;
        default: W = W2;   Th = w2th;   Tl = w2tl;   break;   // z == 4
    }
    if (z == 5) return;  // spare slot (kept for grid shape symmetry)
    wprep_tile(W, Th, Tl, D, D, rowoff, blockIdx.x * 32, blockIdx.y * 32);
    if (z >= 1 && z <= 3 && blockIdx.x == 0 && blockIdx.y == 0) {
        const float* b = (z == 1) ? bq : (z == 2) ? bk : bv;
        for (int j = threadIdx.y * 32 + threadIdx.x; j < D; j += 256)
            bqkv[(z - 1) * D + j] = b[j];
    }
}

__global__ __launch_bounds__(256) void wprep_ff(
    const float* __restrict__ Wf1, const float* __restrict__ Wf2,
    __nv_bfloat16* f1h, __nv_bfloat16* f1l,
    __nv_bfloat16* f2h, __nv_bfloat16* f2l)
{
    const int z = blockIdx.z;
    if (z == 0)
        wprep_tile(Wf1, f1h, f1l, D, DFF, 0, blockIdx.x * 32, blockIdx.y * 32);
    else
        wprep_tile(Wf2, f2h, f2l, DFF, D, 0, blockIdx.y * 32, blockIdx.x * 32);
}

// b_comb[n] = sum_k bo[k] * W2[k, n] + b2[n]
__global__ __launch_bounds__(256) void bias_fold(
    const float* __restrict__ bo, const float* __restrict__ W2,
    const float* __restrict__ b2, float* __restrict__ bcomb)
{
    const int n = blockIdx.x * 256 + threadIdx.x;
    float s = b2[n];
    for (int k = 0; k < D; k++) s += bo[k] * W2[(size_t)k * D + n];
    bcomb[n] = s;
}

// ================= LayerNorm (warp-shuffle reductions) ======================
template<int WF32, int WSPLIT>
__global__ __launch_bounds__(256) void ln_kernel(
    const float* __restrict__ x, const float* __restrict__ g,
    const float* __restrict__ b, float* __restrict__ outf,
    __nv_bfloat16* __restrict__ oh, __nv_bfloat16* __restrict__ ol)
{
    __shared__ float red[8];
    __shared__ float bc[2];
    const int row = blockIdx.x;
    const int tid = threadIdx.x;
    const int lane = tid & 31, warp = tid >> 5;
    float4 v = *(const float4*)(x + (size_t)row * D + tid * 4);

    float s = wred_sum(v.x + v.y + v.z + v.w);
    if (lane == 0) red[warp] = s;
    __syncthreads();
    if (warp == 0) {
        float t = red[lane & 7];
        t += __shfl_xor_sync(0xffffffffu, t, 1);
        t += __shfl_xor_sync(0xffffffffu, t, 2);
        t += __shfl_xor_sync(0xffffffffu, t, 4);
        if (lane == 0) bc[0] = t;
    }
    __syncthreads();
    const float mean = bc[0] * (1.0f / D);
    const float dx = v.x - mean, dy = v.y - mean, dz = v.z - mean, dw = v.w - mean;

    float s2 = wred_sum(dx * dx + dy * dy + dz * dz + dw * dw);
    if (lane == 0) red[warp] = s2;
    __syncthreads();
    if (warp == 0) {
        float t = red[lane & 7];
        t += __shfl_xor_sync(0xffffffffu, t, 1);
        t += __shfl_xor_sync(0xffffffffu, t, 2);
        t += __shfl_xor_sync(0xffffffffu, t, 4);
        if (lane == 0) bc[1] = t;
    }
    __syncthreads();
    const float inv = 1.0f / (sqrtf(bc[1] * (1.0f / D)) + 1e-6f);

    float4 gg = *(const float4*)(g + tid * 4);
    float4 bb = *(const float4*)(b + tid * 4);
    float o0 = gg.x * dx * inv + bb.x;
    float o1 = gg.y * dy * inv + bb.y;
    float o2 = gg.z * dz * inv + bb.z;
    float o3 = gg.w * dw * inv + bb.w;
    const size_t base = (size_t)row * D + tid * 4;
    if (WF32) {
        float4 o4 = {o0, o1, o2, o3};
        *(float4*)(outf + base) = o4;
    }
    if (WSPLIT) {
        float vv[4] = {o0, o1, o2, o3};
        __nv_bfloat16 hs[4], ls[4];
#pragma unroll
        for (int i = 0; i < 4; i++) {
            hs[i] = __float2bfloat16_rn(vv[i]);
            ls[i] = __float2bfloat16_rn(vv[i] - __bfloat162float(hs[i]));
        }
        *(uint2*)(oh + base) = *(uint2*)hs;
        *(uint2*)(ol + base) = *(uint2*)ls;
    }
}

// ================= shared GEMM plumbing ======================================
__device__ __forceinline__ uint32_t swz(int row, int kb) {
    return (uint32_t)(row * 64 + ((kb ^ ((row >> 1) & 3)) << 4));
}

template<int ROWS>
__device__ __forceinline__ void load_tileT(
    const __nv_bfloat16* __restrict__ g, int ld, int row0, int k0, uint32_t sbase, int tid)
{
#pragma unroll
    for (int it = 0; it < ROWS / 64; it++) {
        int c = tid + (it << 8);
        int row = c >> 2, kb = c & 3;
        cpa16(sbase + swz(row, kb), g + (size_t)(row0 + row) * ld + k0 + kb * 8);
    }
}

// 3-pass emulation MMA block: breaks same-accumulator dependency chains
#define EMU_MMA_BLOCK(ACC, A0, A1, A2, A3, L0, L1, L2, L3, BH, BL, NT) do { \
    _Pragma("unroll") \
    for (int _n = 0; _n < (NT); _n++) mma_bf16(ACC[_n], A0, A1, A2, A3, BH[_n][0], BH[_n][1]); \
    _Pragma("unroll") \
    for (int _n = 0; _n < (NT); _n++) mma_bf16(ACC[_n], A0, A1, A2, A3, BL[_n][0], BL[_n][1]); \
    _Pragma("unroll") \
    for (int _n = 0; _n < (NT); _n++) mma_bf16(ACC[_n], L0, L1, L2, L3, BH[_n][0], BH[_n][1]); \
} while (0)

// ================= mma.sync GEMM (2-stage, occ 2): C = A[M,K] @ T[N,K]^T =====
template<int BN, int WF32, int WSPLIT, int RELU, int RESID>
__global__ __launch_bounds__(256, 2) void mma_gemm(
    const __nv_bfloat16* __restrict__ Ah, const __nv_bfloat16* __restrict__ Al,
    const __nv_bfloat16* __restrict__ Bh, const __nv_bfloat16* __restrict__ Bl,
    const float* __restrict__ bias, const float* __restrict__ res,
    float* __restrict__ Cf, __nv_bfloat16* __restrict__ Chi, __nv_bfloat16* __restrict__ Clo,
    int N, int K)
{
    constexpr int MT   = (BN == 128) ? 4 : 2;
    constexpr int BB   = BN * 64;
    constexpr int SA_H = 0, SA_L = 8192, SB_H = 16384;
    constexpr int SB_L = 16384 + BB;
    constexpr int SSZ  = 16384 + 2 * BB;

    extern __shared__ char smem[];
    const uint32_t sb = smem_u32(smem);
    const int tid = threadIdx.x, wid = tid >> 5, lane = tid & 31;
    const int warp_m = (BN == 128) ? (wid & 1) : (wid & 3);
    const int warp_n = (BN == 128) ? (wid >> 1) : (wid >> 2);
    const int brow = blockIdx.y * 128, bcol = blockIdx.x * BN;

    float acc[MT][4][4];
#pragma unroll
    for (int a = 0; a < MT; a++)
#pragma unroll
        for (int b = 0; b < 4; b++)
#pragma unroll
            for (int c = 0; c < 4; c++) acc[a][b][c] = 0.0f;

    const int nch = K >> 5;
    load_tileT<128>(Ah, K, brow, 0, sb + SA_H, tid);
    load_tileT<128>(Al, K, brow, 0, sb + SA_L, tid);
    load_tileT<BN>(Bh, K, bcol, 0, sb + SB_H, tid);
    load_tileT<BN>(Bl, K, bcol, 0, sb + SB_L, tid);
    CPA_COMMIT();

    const int tileA = lane >> 3;
    const int rinA  = (lane & 7) + ((tileA & 1) << 3);
    const int kbA   = tileA >> 1;
    const int i16   = lane & 15;
    const int rinB  = i16 & 7;
    const int kbB   = i16 >> 3;

    for (int i = 0; i < nch; i++) {
        if (i + 1 < nch) {
            const uint32_t st = sb + ((i + 1) & 1) * SSZ;
            const int k0 = (i + 1) << 5;
            load_tileT<128>(Ah, K, brow, k0, st + SA_H, tid);
            load_tileT<128>(Al, K, brow, k0, st + SA_L, tid);
            load_tileT<BN>(Bh, K, bcol, k0, st + SB_H, tid);
            load_tileT<BN>(Bl, K, bcol, k0, st + SB_L, tid);
            CPA_COMMIT();
            asm volatile("cp.async.wait_group 1;" ::: "memory");
        } else {
            asm volatile("cp.async.wait_group 0;" ::: "memory");
        }
        __syncthreads();

        const uint32_t st = sb + (i & 1) * SSZ;
#pragma unroll
        for (int ks = 0; ks < 2; ks++) {
            uint32_t bh[4][2], bl[4][2];
#pragma unroll
            for (int nt = 0; nt < 4; nt++) {
                const int rowb = warp_n * 32 + nt * 8 + rinB;
                const uint32_t off = swz(rowb, (ks << 1) + kbB);
                ldm_x2(bh[nt][0], bh[nt][1], st + SB_H + off);
                ldm_x2(bl[nt][0], bl[nt][1], st + SB_L + off);
            }
#pragma unroll
            for (int mt = 0; mt < MT; mt++) {
                const int rowa = warp_m * (MT * 16) + mt * 16 + rinA;
                const uint32_t off = swz(rowa, (ks << 1) + kbA);
                uint32_t a0, a1, a2, a3, l0, l1, l2, l3;
                ldm_x4(a0, a1, a2, a3, st + SA_H + off);
                ldm_x4(l0, l1, l2, l3, st + SA_L + off);
                EMU_MMA_BLOCK(acc[mt], a0, a1, a2, a3, l0, l1, l2, l3, bh, bl, 4);
            }
        }
        __syncthreads();
    }

    const int g4 = lane >> 2, t4 = lane & 3;
#pragma unroll
    for (int mt = 0; mt < MT; mt++) {
#pragma unroll
        for (int half = 0; half < 2; half++) {
            const int row = brow + warp_m * (MT * 16) + mt * 16 + g4 + half * 8;
#pragma unroll
            for (int nt = 0; nt < 4; nt++) {
                const int col = bcol + warp_n * 32 + nt * 8 + t4 * 2;
                float v0 = acc[mt][nt][half * 2 + 0] + bias[col];
                float v1 = acc[mt][nt][half * 2 + 1] + bias[col + 1];
                if (RELU) { v0 = fmaxf(v0, 0.0f); v1 = fmaxf(v1, 0.0f); }
                const size_t o = (size_t)row * N + col;
                if (RESID) { v0 += res[o]; v1 += res[o + 1]; }
                if (WF32) {
                    float2 f2 = {v0, v1};
                    *(float2*)(Cf + o) = f2;
                }
                if (WSPLIT) {
                    __nv_bfloat16 h0 = __float2bfloat16_rn(v0);
                    __nv_bfloat16 h1 = __float2bfloat16_rn(v1);
                    __nv_bfloat16 q0 = __float2bfloat16_rn(v0 - __bfloat162float(h0));
                    __nv_bfloat16 q1 = __float2bfloat16_rn(v1 - __bfloat162float(h1));
                    __nv_bfloat162 hp = {h0, h1}, lp = {q0, q1};
                    *(__nv_bfloat162*)(Chi + o) = hp;
                    *(__nv_bfloat162*)(Clo + o) = lp;
                }
            }
        }
    }
}

#define GSTG_128 32768
#define GSMEM_128 (2 * GSTG_128)
#define GSTG_64 24576
#define GSMEM_64 (2 * GSTG_64)

// ================= score mma: S = (Q K^T)/8, causal ==========================
#define STG_A_H 0
#define STG_A_L 8192
#define STG_B_H 16384
#define STG_B_L 24576
#define STG_SZ  32768
#define SCORE_SMEM (2 * STG_SZ)

__global__ __launch_bounds__(256, 2) void score_mma(
    const __nv_bfloat16* __restrict__ qh, const __nv_bfloat16* __restrict__ ql,
    const __nv_bfloat16* __restrict__ kh, const __nv_bfloat16* __restrict__ kl,
    float* __restrict__ attn)
{
    const int brow = blockIdx.y * 128, bcol = blockIdx.x * 128;
    if (bcol >= brow + 128) return;
    const int h = blockIdx.z;
    const __nv_bfloat16* Ah = qh + h * DK;
    const __nv_bfloat16* Al = ql + h * DK;
    const __nv_bfloat16* Bh = kh + h * DK;
    const __nv_bfloat16* Bl = kl + h * DK;

    extern __shared__ char smem[];
    const uint32_t sb = smem_u32(smem);
    const int tid = threadIdx.x, wid = tid >> 5, lane = tid & 31;
    const int warp_m = wid & 1, warp_n = wid >> 1;

    float acc[4][4][4];
#pragma unroll
    for (int a = 0; a < 4; a++)
#pragma unroll
        for (int b = 0; b < 4; b++)
#pragma unroll
            for (int c = 0; c < 4; c++) acc[a][b][c] = 0.0f;

    load_tileT<128>(Ah, 3 * D, brow, 0, sb + STG_A_H, tid);
    load_tileT<128>(Al, 3 * D, brow, 0, sb + STG_A_L, tid);
    load_tileT<128>(Bh, 3 * D, bcol, 0, sb + STG_B_H, tid);
    load_tileT<128>(Bl, 3 * D, bcol, 0, sb + STG_B_L, tid);
    CPA_COMMIT();

    const int tileA = lane >> 3;
    const int rinA  = (lane & 7) + ((tileA & 1) << 3);
    const int kbA   = tileA >> 1;
    const int i16   = lane & 15;
    const int rinB  = i16 & 7;
    const int kbB   = i16 >> 3;

    for (int i = 0; i < 2; i++) {
        if (i == 0) {
            const uint32_t st = sb + STG_SZ;
            load_tileT<128>(Ah, 3 * D, brow, 32, st + STG_A_H, tid);
            load_tileT<128>(Al, 3 * D, brow, 32, st + STG_A_L, tid);
            load_tileT<128>(Bh, 3 * D, bcol, 32, st + STG_B_H, tid);
            load_tileT<128>(Bl, 3 * D, bcol, 32, st + STG_B_L, tid);
            CPA_COMMIT();
            asm volatile("cp.async.wait_group 1;" ::: "memory");
        } else {
            asm volatile("cp.async.wait_group 0;" ::: "memory");
        }
        __syncthreads();

        const uint32_t st = sb + (i & 1) * STG_SZ;
#pragma unroll
        for (int ks = 0; ks < 2; ks++) {
            uint32_t bh[4][2], bl[4][2];
#pragma unroll
            for (int nt = 0; nt < 4; nt++) {
                const int rowb = warp_n * 32 + nt * 8 + rinB;
                const uint32_t off = swz(rowb, (ks << 1) + kbB);
                ldm_x2(bh[nt][0], bh[nt][1], st + STG_B_H + off);
                ldm_x2(bl[nt][0], bl[nt][1], st + STG_B_L + off);
            }
#pragma unroll
            for (int mt = 0; mt < 4; mt++) {
                const int rowa = warp_m * 64 + mt * 16 + rinA;
                const uint32_t off = swz(rowa, (ks << 1) + kbA);
                uint32_t a0, a1, a2, a3, l0, l1, l2, l3;
                ldm_x4(a0, a1, a2, a3, st + STG_A_H + off);
                ldm_x4(l0, l1, l2, l3, st + STG_A_L + off);
                EMU_MMA_BLOCK(acc[mt], a0, a1, a2, a3, l0, l1, l2, l3, bh, bl, 4);
            }
        }
        __syncthreads();
    }

    const int g4 = lane >> 2, t4 = lane & 3;
#pragma unroll
    for (int mt = 0; mt < 4; mt++) {
#pragma unroll
        for (int half = 0; half < 2; half++) {
            const int row = brow + warp_m * 64 + mt * 16 + g4 + half * 8;
            float* arow = attn + ((size_t)h * SQ + row) * SQ;
#pragma unroll
            for (int nt = 0; nt < 4; nt++) {
                const int col = bcol + warp_n * 32 + nt * 8 + t4 * 2;
                if (col <= row)     arow[col]     = acc[mt][nt][half * 2 + 0] * 0.125f;
                if (col + 1 <= row) arow[col + 1] = acc[mt][nt][half * 2 + 1] * 0.125f;
            }
        }
    }
}

// ================= softmax (warp-shuffle): fp32 out + bf16 hi/lo =============
__global__ __launch_bounds__(256) void softmax_kernel(
    float* __restrict__ attn,
    __nv_bfloat16* __restrict__ ah, __nv_bfloat16* __restrict__ al)
{
    __shared__ float p[SQ];
    __shared__ float red[8];
    __shared__ float bc[2];
    const int i   = blockIdx.x;
    const int h   = blockIdx.y;
    const int tid = threadIdx.x;
    const int lane = tid & 31, warp = tid >> 5;
    const size_t rb = ((size_t)h * SQ + i) * SQ;
    float* row = attn + rb;

    float m = -INFINITY;
    for (int j = tid; j <= i; j += 256) { float s = row[j]; p[j] = s; m = fmaxf(m, s); }
    m = wred_max(m);
    if (lane == 0) red[warp] = m;
    __syncthreads();
    if (warp == 0) {
        float t = red[lane & 7];
        t = fmaxf(t, __shfl_xor_sync(0xffffffffu, t, 1));
        t = fmaxf(t, __shfl_xor_sync(0xffffffffu, t, 2));
        t = fmaxf(t, __shfl_xor_sync(0xffffffffu, t, 4));
        if (lane == 0) bc[0] = t;
    }
    __syncthreads();
    const float mx = bc[0];

    float sum = 0.0f;
    for (int j = tid; j <= i; j += 256) { float e = __expf(p[j] - mx); p[j] = e; sum += e; }
    sum = wred_sum(sum);
    __syncthreads();
    if (lane == 0) red[warp] = sum;
    __syncthreads();
    if (warp == 0) {
        float t = red[lane & 7];
        t += __shfl_xor_sync(0xffffffffu, t, 1);
        t += __shfl_xor_sync(0xffffffffu, t, 2);
        t += __shfl_xor_sync(0xffffffffu, t, 4);
        if (lane == 0) bc[1] = t;
    }
    __syncthreads();
    const float inv = 1.0f / bc[1];

    const int lim = ((i >> 7) + 1) << 7;
    for (int j = tid; j <= i; j += 256) {
        float w = p[j] * inv;
        row[j] = w;
        __nv_bfloat16 hh = __float2bfloat16_rn(w);
        ah[rb + j] = hh;
        al[rb + j] = __float2bfloat16_rn(w - __bfloat162float(hh));
    }

    // vectorized zero fills
    const int zs = i + 1;
    const int za = (zs + 3) & ~3;
    // fp32 zeros [zs, SQ)
    if (tid < za - zs && zs + tid < SQ) row[zs + tid] = 0.0f;
    const float4 zf4 = {0.0f, 0.0f, 0.0f, 0.0f};
    for (int j = za + tid * 4; j < SQ; j += 1024) *(float4*)(row + j) = zf4;
    // bf16 zeros [zs, lim)
    const __nv_bfloat16 z = __float2bfloat16_rn(0.0f);
    if (tid < za - zs && zs + tid < lim) { ah[rb + zs + tid] = z; al[rb + zs + tid] = z; }
    const uint2 zu2 = {0u, 0u};
    for (int j = za + tid * 4; j < lim; j += 1024) {
        *(uint2*)(ah + rb + j) = zu2;
        *(uint2*)(al + rb + j) = zu2;
    }
}

// ================= AV mma (2-stage, occ 2): ctx = P @ V ======================
#define AV_A_H 0
#define AV_A_L 8192
#define AV_B_H 16384
#define AV_B_L 20480
#define AV_STG 24576
#define AV_SMEM (2 * AV_STG)

__global__ __launch_bounds__(256, 2) void av_mma(
    const __nv_bfloat16* __restrict__ ah, const __nv_bfloat16* __restrict__ al,
    const __nv_bfloat16* __restrict__ vh, const __nv_bfloat16* __restrict__ vl,
    __nv_bfloat16* __restrict__ ch, __nv_bfloat16* __restrict__ cl)
{
    const int brow = blockIdx.x * 128;
    const int h    = blockIdx.y;
    const __nv_bfloat16* Ah = ah + (size_t)h * SQ * SQ;
    const __nv_bfloat16* Al = al + (size_t)h * SQ * SQ;
    const __nv_bfloat16* Vh = vh + 2 * D + h * DK;
    const __nv_bfloat16* Vl = vl + 2 * D + h * DK;

    extern __shared__ char smem[];
    const uint32_t sb = smem_u32(smem);
    const int tid = threadIdx.x, wid = tid >> 5, lane = tid & 31;
    const int warp_m = wid & 3;
    const int warp_n = wid >> 2;

    float acc[2][4][4];
#pragma unroll
    for (int a = 0; a < 2; a++)
#pragma unroll
        for (int b = 0; b < 4; b++)
#pragma unroll
            for (int c = 0; c < 4; c++) acc[a][b][c] = 0.0f;

    auto load_b = [&](const __nv_bfloat16* V, int k0, uint32_t sbase) {
        int r = tid >> 3, g = tid & 7;
        cpa16(sbase + (uint32_t)(r * 128 + ((g ^ (r & 7)) << 4)),
              V + (size_t)(k0 + r) * (3 * D) + g * 8);
    };
    auto load_stage = [&](int ci, uint32_t st) {
        const int k0 = ci << 5;
        load_tileT<128>(Ah, SQ, brow, k0, st + AV_A_H, tid);
        load_tileT<128>(Al, SQ, brow, k0, st + AV_A_L, tid);
        load_b(Vh, k0, st + AV_B_H);
        load_b(Vl, k0, st + AV_B_L);
        CPA_COMMIT();
    };

    const int nch = (brow >> 5) + 4;
    load_stage(0, sb);

    const int tileA = lane >> 3;
    const int rinA  = (lane & 7) + ((tileA & 1) << 3);
    const int kbA   = tileA >> 1;
    const int i16   = lane & 15;

    for (int i = 0; i < nch; i++) {
        if (i + 1 < nch) {
            load_stage(i + 1, sb + ((i + 1) & 1) * AV_STG);
            asm volatile("cp.async.wait_group 1;" ::: "memory");
        } else {
            asm volatile("cp.async.wait_group 0;" ::: "memory");
        }
        __syncthreads();

        const uint32_t st = sb + (i & 1) * AV_STG;
#pragma unroll
        for (int ks = 0; ks < 2; ks++) {
            uint32_t bh[4][2], bl[4][2];
#pragma unroll
            for (int nt = 0; nt < 4; nt++) {
                const int krow = ks * 16 + i16;
                const int gB = warp_n * 4 + nt;
                const uint32_t off = (uint32_t)(krow * 128 + ((gB ^ (krow & 7)) << 4));
                ldm_x2t(bh[nt][0], bh[nt][1], st + AV_B_H + off);
                ldm_x2t(bl[nt][0], bl[nt][1], st + AV_B_L + off);
            }
#pragma unroll
            for (int mt = 0; mt < 2; mt++) {
                const int rowa = warp_m * 32 + mt * 16 + rinA;
                const uint32_t off = swz(rowa, (ks << 1) + kbA);
                uint32_t a0, a1, a2, a3, l0, l1, l2, l3;
                ldm_x4(a0, a1, a2, a3, st + AV_A_H + off);
                ldm_x4(l0, l1, l2, l3, st + AV_A_L + off);
                EMU_MMA_BLOCK(acc[mt], a0, a1, a2, a3, l0, l1, l2, l3, bh, bl, 4);
            }
        }
        __syncthreads();
    }

    const int g4 = lane >> 2, t4 = lane & 3;
#pragma unroll
    for (int mt = 0; mt < 2; mt++) {
#pragma unroll
        for (int half = 0; half < 2; half++) {
            const int row = brow + warp_m * 32 + mt * 16 + g4 + half * 8;
#pragma unroll
            for (int nt = 0; nt < 4; nt++) {
                const int col = h * DK + warp_n * 32 + nt * 8 + t4 * 2;
                float v0 = acc[mt][nt][half * 2 + 0];
                float v1 = acc[mt][nt][half * 2 + 1];
                const size_t o = (size_t)row * D + col;
                __nv_bfloat16 h0 = __float2bfloat16_rn(v0);
                __nv_bfloat16 h1 = __float2bfloat16_rn(v1);
                __nv_bfloat16 q0 = __float2bfloat16_rn(v0 - __bfloat162float(h0));
                __nv_bfloat16 q1 = __float2bfloat16_rn(v1 - __bfloat162float(h1));
                __nv_bfloat162 hp = {h0, h1}, lp = {q0, q1};
                *(__nv_bfloat162*)(ch + o) = hp;
                *(__nv_bfloat162*)(cl + o) = lp;
            }
        }
    }
}

// ================= host driver =================
struct Scratch {
    __nv_bfloat16 *nxh, *nxl, *hh, *hl, *qkvh, *qkvl, *ctxh, *ctxl, *n2h, *n2l, *ff1h, *ff1l;
    __nv_bfloat16 *attnh, *attnl;
    __nv_bfloat16 *winth, *wintl, *wqkvth, *wqkvtl, *w2th, *w2tl, *wf1th, *wf1tl, *wf2th, *wf2tl;
    __nv_bfloat16 *wonth, *wontl, *combh, *combl;
    float *p1, *n2, *attn, *bqkv, *bcomb, *zero;
};

static Scratch get_scratch() {
    static Scratch s = [] {
        Scratch t;
        void* p;
        cudaGetSymbolAddress(&p, g_nx_h);   t.nxh = (__nv_bfloat16*)p;
        cudaGetSymbolAddress(&p, g_nx_l);   t.nxl = (__nv_bfloat16*)p;
        cudaGetSymbolAddress(&p, g_h_h);    t.hh  = (__nv_bfloat16*)p;
        cudaGetSymbolAddress(&p, g_h_l);    t.hl  = (__nv_bfloat16*)p;
        cudaGetSymbolAddress(&p, g_qkv_h);  t.qkvh = (__nv_bfloat16*)p;
        cudaGetSymbolAddress(&p, g_qkv_l);  t.qkvl = (__nv_bfloat16*)p;
        cudaGetSymbolAddress(&p, g_ctx_h);  t.ctxh = (__nv_bfloat16*)p;
        cudaGetSymbolAddress(&p, g_ctx_l);  t.ctxl = (__nv_bfloat16*)p;
        cudaGetSymbolAddress(&p, g_n2_h);   t.n2h = (__nv_bfloat16*)p;
        cudaGetSymbolAddress(&p, g_n2_l);   t.n2l = (__nv_bfloat16*)p;
        cudaGetSymbolAddress(&p, g_ff1_h);  t.ff1h = (__nv_bfloat16*)p;
        cudaGetSymbolAddress(&p, g_ff1_l);  t.ff1l = (__nv_bfloat16*)p;
        cudaGetSymbolAddress(&p, g_attn_h); t.attnh = (__nv_bfloat16*)p;
        cudaGetSymbolAddress(&p, g_attn_l); t.attnl = (__nv_bfloat16*)p;
        cudaGetSymbolAddress(&p, g_wint_h); t.winth = (__nv_bfloat16*)p;
        cudaGetSymbolAddress(&p, g_wint_l); t.wintl = (__nv_bfloat16*)p;
        cudaGetSymbolAddress(&p, g_wqkvt_h); t.wqkvth = (__nv_bfloat16*)p;
        cudaGetSymbolAddress(&p, g_wqkvt_l); t.wqkvtl = (__nv_bfloat16*)p;
        cudaGetSymbolAddress(&p, g_w2t_h);  t.w2th = (__nv_bfloat16*)p;
        cudaGetSymbolAddress(&p, g_w2t_l);  t.w2tl = (__nv_bfloat16*)p;
        cudaGetSymbolAddress(&p, g_wf1t_h); t.wf1th = (__nv_bfloat16*)p;
        cudaGetSymbolAddress(&p, g_wf1t_l); t.wf1tl = (__nv_bfloat16*)p;
        cudaGetSymbolAddress(&p, g_wf2t_h); t.wf2th = (__nv_bfloat16*)p;
        cudaGetSymbolAddress(&p, g_wf2t_l); t.wf2tl = (__nv_bfloat16*)p;
        cudaGetSymbolAddress(&p, g_wo_nt_h); t.wonth = (__nv_bfloat16*)p;
        cudaGetSymbolAddress(&p, g_wo_nt_l); t.wontl = (__nv_bfloat16*)p;
        cudaGetSymbolAddress(&p, g_comb_h); t.combh = (__nv_bfloat16*)p;
        cudaGetSymbolAddress(&p, g_comb_l); t.combl = (__nv_bfloat16*)p;
        cudaGetSymbolAddress(&p, g_p1);     t.p1  = (float*)p;
        cudaGetSymbolAddress(&p, g_n2);     t.n2  = (float*)p;
        cudaGetSymbolAddress(&p, g_attn_scratch); t.attn = (float*)p;
        cudaGetSymbolAddress(&p, g_bqkv);   t.bqkv = (float*)p;
        cudaGetSymbolAddress(&p, g_bcomb);  t.bcomb = (float*)p;
        cudaGetSymbolAddress(&p, g_zero);   t.zero = (float*)p;
        cudaFuncSetAttribute((const void*)mma_gemm<64,0,1,0,0>,  cudaFuncAttributeMaxDynamicSharedMemorySize, GSMEM_64);
        cudaFuncSetAttribute((const void*)mma_gemm<64,1,0,0,1>,  cudaFuncAttributeMaxDynamicSharedMemorySize, GSMEM_64);
        cudaFuncSetAttribute((const void*)mma_gemm<128,0,1,0,0>, cudaFuncAttributeMaxDynamicSharedMemorySize, GSMEM_128);
        cudaFuncSetAttribute((const void*)mma_gemm<128,0,1,1,0>, cudaFuncAttributeMaxDynamicSharedMemorySize, GSMEM_128);
        cudaFuncSetAttribute((const void*)score_mma, cudaFuncAttributeMaxDynamicSharedMemorySize, SCORE_SMEM);
        cudaFuncSetAttribute((const void*)av_mma,    cudaFuncAttributeMaxDynamicSharedMemorySize, AV_SMEM);
        return t;
    }();
    return s;
}

extern "C" void kernel_launch(void* const* d_in, const int* in_sizes, int n_in,
                              void* d_out, int out_size)
{
    const float* x     = (const float*)d_in[0];
    const float* g1    = (const float*)d_in[1];
    const float* beta1 = (const float*)d_in[2];
    const float* W_in  = (const float*)d_in[3];
    const float* b_in  = (const float*)d_in[4];
    const float* Wq    = (const float*)d_in[5];
    const float* bq    = (const float*)d_in[6];
    const float* Wk    = (const float*)d_in[7];
    const float* bk    = (const float*)d_in[8];
    const float* Wv    = (const float*)d_in[9];
    const float* bv    = (const float*)d_in[10];
    const float* Wo    = (const float*)d_in[11];
    const float* bo    = (const float*)d_in[12];
    const float* W2    = (const float*)d_in[13];
    const float* b2    = (const float*)d_in[14];
    const float* g2    = (const float*)d_in[15];
    const float* beta2 = (const float*)d_in[16];
    const float* Wf1   = (const float*)d_in[17];
    const float* bf1   = (const float*)d_in[18];
    const float* Wf2   = (const float*)d_in[19];
    const float* bf2   = (const float*)d_in[20];

    Scratch s = get_scratch();

    float* out  = (float*)d_out;
    const long long full = (long long)SQ * D + (long long)NH * SQ * SQ;
    float* attn = ((long long)out_size >= full) ? (out + (size_t)SQ * D) : s.attn;

    dim3 blk(256);
    dim3 wblk(32, 8);

    // #1: weight prep (z=0..6: W_in, Wq, Wk, Wv, spare, W2, Wo-straight)
    wprep_dd<<<dim3(32, 32, 7), wblk>>>(
        W_in, Wq, Wk, Wv, Wo, W2, bq, bk, bv,
        s.winth, s.wintl, s.wqkvth, s.wqkvtl, s.wonth, s.wontl, s.w2th, s.w2tl, s.bqkv);
    // #2: ff weight prep
    wprep_ff<<<dim3(128, 32, 2), wblk>>>(Wf1, Wf2, s.wf1th, s.wf1tl, s.wf2th, s.wf2tl);
    // #3: b_comb = bo@W2 + b2
    bias_fold<<<4, 256>>>(bo, W2, b2, s.bcomb);
    // #4: comb[b,a] = sum_mid W2T[b,mid]*Wo[a,mid]  (= (Wo@W2) in B-operand layout)
    mma_gemm<64,0,1,0,0><<<dim3(D/64, D/128), 256, GSMEM_64>>>(
        s.w2th, s.w2tl, s.wonth, s.wontl, s.zero, nullptr, nullptr, s.combh, s.combl, D, D);
    // #5: LN1 -> split
    ln_kernel<0,1><<<SQ, blk>>>(x, g1, beta1, nullptr, s.nxh, s.nxl);
    // #6: h = nx @ W_in + b_in   [ncu -s 5 captures this]
    mma_gemm<64,0,1,0,0><<<dim3(D/64, SQ/128), 256, GSMEM_64>>>(
        s.nxh, s.nxl, s.winth, s.wintl, b_in, nullptr, nullptr, s.hh, s.hl, D, D);
    // #7: qkv (packed N=3072)
    mma_gemm<128,0,1,0,0><<<dim3(3*D/128, SQ/128), 256, GSMEM_128>>>(
        s.hh, s.hl, s.wqkvth, s.wqkvtl, s.bqkv, nullptr, nullptr, s.qkvh, s.qkvl, 3*D, D);
    // #8: scores
    score_mma<<<dim3(SQ/128, SQ/128, NH), 256, SCORE_SMEM>>>(
        s.qkvh, s.qkvl, s.qkvh + D, s.qkvl + D, attn);
    // #9: softmax
    softmax_kernel<<<dim3(SQ, NH), blk>>>(attn, s.attnh, s.attnl);
    // #10: AV
    av_mma<<<dim3(SQ/128, NH), 256, AV_SMEM>>>(
        s.attnh, s.attnl, s.qkvh, s.qkvl, s.ctxh, s.ctxl);
    // #11: p1 = x + ctx @ (Wo@W2) + b_comb   (fused Wo/W2)
    mma_gemm<64,1,0,0,1><<<dim3(D/64, SQ/128), 256, GSMEM_64>>>(
        s.ctxh, s.ctxl, s.combh, s.combl, s.bcomb, x, s.p1, nullptr, nullptr, D, D);
    // #12: LN2
    ln_kernel<1,1><<<SQ, blk>>>(s.p1, g2, beta2, s.n2, s.n2h, s.n2l);
    // #13: ff1 = relu(n2 @ Wf1 + bf1)
    mma_gemm<128,0,1,1,0><<<dim3(DFF/128, SQ/128), 256, GSMEM_128>>>(
        s.n2h, s.n2l, s.wf1th, s.wf1tl, bf1, nullptr, nullptr, s.ff1h, s.ff1l, DFF, D);
    // #14: out = n2 + ff1 @ Wf2 + bf2
    mma_gemm<64,1,0,0,1><<<dim3(D/64, SQ/128), 256, GSMEM_64>>>(
        s.ff1h, s.ff1l, s.wf2th, s.wf2tl, bf2, s.n2, out, nullptr, nullptr, D, DFF);
}

// round 11
// speedup vs baseline: 1.0204x; 1.0204x over previous
#include <cuda_runtime.h>
#include <cuda_bf16.h>
#include <math.h>
#include <stdint.h>

#define SQ   2048
#define D    1024
#define NH   16
#define DK   64
#define DFF  4096

// ================= PTX helpers (baseline ISA only) ==========================
__device__ __forceinline__ uint32_t smem_u32(const void* p) {
    uint32_t a;
    asm("{ .reg .u64 t; cvta.to.shared.u64 t, %1; cvt.u32.u64 %0, t; }" : "=r"(a) : "l"(p));
    return a;
}
__device__ __forceinline__ void cpa16(uint32_t dst, const void* src) {
    asm volatile("cp.async.cg.shared.global [%0], [%1], 16;" :: "r"(dst), "l"(src));
}
#define CPA_COMMIT() asm volatile("cp.async.commit_group;" ::: "memory")
__device__ __forceinline__ void ldm_x4(uint32_t& r0, uint32_t& r1, uint32_t& r2, uint32_t& r3, uint32_t addr) {
    asm volatile("ldmatrix.sync.aligned.m8n8.x4.shared.b16 {%0,%1,%2,%3}, [%4];"
                 : "=r"(r0), "=r"(r1), "=r"(r2), "=r"(r3) : "r"(addr));
}
__device__ __forceinline__ void ldm_x2(uint32_t& r0, uint32_t& r1, uint32_t addr) {
    asm volatile("ldmatrix.sync.aligned.m8n8.x2.shared.b16 {%0,%1}, [%2];"
                 : "=r"(r0), "=r"(r1) : "r"(addr));
}
__device__ __forceinline__ void ldm_x2t(uint32_t& r0, uint32_t& r1, uint32_t addr) {
    asm volatile("ldmatrix.sync.aligned.m8n8.x2.trans.shared.b16 {%0,%1}, [%2];"
                 : "=r"(r0), "=r"(r1) : "r"(addr));
}
__device__ __forceinline__ void mma_bf16(float* c, uint32_t a0, uint32_t a1, uint32_t a2, uint32_t a3,
                                         uint32_t b0, uint32_t b1) {
    asm volatile("mma.sync.aligned.m16n8k16.row.col.f32.bf16.bf16.f32 "
                 "{%0,%1,%2,%3}, {%4,%5,%6,%7}, {%8,%9}, {%0,%1,%2,%3};"
                 : "+f"(c[0]), "+f"(c[1]), "+f"(c[2]), "+f"(c[3])
                 : "r"(a0), "r"(a1), "r"(a2), "r"(a3), "r"(b0), "r"(b1));
}
__device__ __forceinline__ float wred_max(float v) {
#pragma unroll
    for (int o = 16; o > 0; o >>= 1) v = fmaxf(v, __shfl_xor_sync(0xffffffffu, v, o));
    return v;
}
__device__ __forceinline__ float wred_sum(float v) {
#pragma unroll
    for (int o = 16; o > 0; o >>= 1) v += __shfl_xor_sync(0xffffffffu, v, o);
    return v;
}

// ================= scratch =================
__device__ __nv_bfloat16 g_nx_h[SQ * D],  g_nx_l[SQ * D];
__device__ __nv_bfloat16 g_h_h[SQ * D],   g_h_l[SQ * D];
__device__ __nv_bfloat16 g_qkv_h[SQ * 3 * D], g_qkv_l[SQ * 3 * D];
__device__ __nv_bfloat16 g_ctx_h[SQ * D], g_ctx_l[SQ * D];
__device__ __nv_bfloat16 g_mha_h[SQ * D], g_mha_l[SQ * D];
__device__ float         g_p1[SQ * D];
__device__ float         g_n2[SQ * D];
__device__ __nv_bfloat16 g_n2_h[SQ * D],  g_n2_l[SQ * D];
__device__ __nv_bfloat16 g_ff1_h[SQ * DFF], g_ff1_l[SQ * DFF];
__device__ float         g_attn_scratch[(size_t)NH * SQ * SQ];
__device__ __nv_bfloat16 g_attn_h[(size_t)NH * SQ * SQ];
__device__ __nv_bfloat16 g_attn_l[(size_t)NH * SQ * SQ];
// transposed/split weights [N, K]
__device__ __nv_bfloat16 g_wint_h[D * D],      g_wint_l[D * D];
__device__ __nv_bfloat16 g_wqkvt_h[3 * D * D], g_wqkvt_l[3 * D * D];
__device__ __nv_bfloat16 g_wot_h[D * D],       g_wot_l[D * D];
__device__ __nv_bfloat16 g_w2t_h[D * D],       g_w2t_l[D * D];
__device__ __nv_bfloat16 g_wf1t_h[DFF * D],    g_wf1t_l[DFF * D];
__device__ __nv_bfloat16 g_wf2t_h[D * DFF],    g_wf2t_l[D * DFF];
__device__ float         g_bqkv[3 * D];

// ================= batched weight prep ======================================
__device__ __forceinline__ void wprep_tile(
    const float* __restrict__ W, __nv_bfloat16* __restrict__ Th,
    __nv_bfloat16* __restrict__ Tl, int K, int N, int rowoff, int n0, int k0)
{
    __shared__ float t[32][33];
    const int tx = threadIdx.x, ty = threadIdx.y;
    for (int i = ty; i < 32; i += 8)
        t[i][tx] = W[(size_t)(k0 + i) * N + n0 + tx];
    __syncthreads();
    for (int i = ty; i < 32; i += 8) {
        float v = t[tx][i];
        __nv_bfloat16 h = __float2bfloat16_rn(v);
        size_t o = (size_t)(rowoff + n0 + i) * K + k0 + tx;
        Th[o] = h;
        Tl[o] = __float2bfloat16_rn(v - __bfloat162float(h));
    }
}

__global__ __launch_bounds__(256) void wprep_dd(
    const float* __restrict__ W_in, const float* __restrict__ Wq,
    const float* __restrict__ Wk,   const float* __restrict__ Wv,
    const float* __restrict__ Wo,   const float* __restrict__ W2,
    const float* __restrict__ bq,   const float* __restrict__ bk,
    const float* __restrict__ bv,
    __nv_bfloat16* winth, __nv_bfloat16* wintl,
    __nv_bfloat16* wqkvth, __nv_bfloat16* wqkvtl,
    __nv_bfloat16* woth, __nv_bfloat16* wotl,
    __nv_bfloat16* w2th, __nv_bfloat16* w2tl, float* bqkv)
{
    const int z = blockIdx.z;
    const float* W; __nv_bfloat16 *Th, *Tl; int rowoff = 0;
    switch (z) {
        case 0:  W = W_in; Th = winth;  Tl = wintl;  break;
        case 1:  W = Wq;   Th = wqkvth; Tl = wqkvtl; rowoff = 0;     break;
        case 2:  W = Wk;   Th = wqkvth; Tl = wqkvtl; rowoff = D;     break;
        case 3:  W = Wv;   Th = wqkvth; Tl = wqkvtl; rowoff = 2 * D; break;
        case 4:  W = Wo;   Th = woth;   Tl = wotl;   break;
        default: W = W2;   Th = w2th;   Tl = w2tl;   break;
    }
    wprep_tile(W, Th, Tl, D, D, rowoff, blockIdx.x * 32, blockIdx.y * 32);
    if (z >= 1 && z <= 3 && blockIdx.x == 0 && blockIdx.y == 0) {
        const float* b = (z == 1) ? bq : (z == 2) ? bk : bv;
        for (int j = threadIdx.y * 32 + threadIdx.x; j < D; j += 256)
            bqkv[(z - 1) * D + j] = b[j];
    }
}

__global__ __launch_bounds__(256) void wprep_ff(
    const float* __restrict__ Wf1, const float* __restrict__ Wf2,
    __nv_bfloat16* f1h, __nv_bfloat16* f1l,
    __nv_bfloat16* f2h, __nv_bfloat16* f2l)
{
    const int z = blockIdx.z;
    if (z == 0)
        wprep_tile(Wf1, f1h, f1l, D, DFF, 0, blockIdx.x * 32, blockIdx.y * 32);
    else
        wprep_tile(Wf2, f2h, f2l, DFF, D, 0, blockIdx.y * 32, blockIdx.x * 32);
}

// ================= LayerNorm (warp-shuffle reductions) ======================
template<int WF32, int WSPLIT>
__global__ __launch_bounds__(256) void ln_kernel(
    const float* __restrict__ x, const float* __restrict__ g,
    const float* __restrict__ b, float* __restrict__ outf,
    __nv_bfloat16* __restrict__ oh, __nv_bfloat16* __restrict__ ol)
{
    __shared__ float red[8];
    __shared__ float bc[2];
    const int row = blockIdx.x;
    const int tid = threadIdx.x;
    const int lane = tid & 31, warp = tid >> 5;
    float4 v = *(const float4*)(x + (size_t)row * D + tid * 4);

    float s = wred_sum(v.x + v.y + v.z + v.w);
    if (lane == 0) red[warp] = s;
    __syncthreads();
    if (warp == 0) {
        float t = red[lane & 7];
        t += __shfl_xor_sync(0xffffffffu, t, 1);
        t += __shfl_xor_sync(0xffffffffu, t, 2);
        t += __shfl_xor_sync(0xffffffffu, t, 4);
        if (lane == 0) bc[0] = t;
    }
    __syncthreads();
    const float mean = bc[0] * (1.0f / D);
    const float dx = v.x - mean, dy = v.y - mean, dz = v.z - mean, dw = v.w - mean;

    float s2 = wred_sum(dx * dx + dy * dy + dz * dz + dw * dw);
    if (lane == 0) red[warp] = s2;
    __syncthreads();
    if (warp == 0) {
        float t = red[lane & 7];
        t += __shfl_xor_sync(0xffffffffu, t, 1);
        t += __shfl_xor_sync(0xffffffffu, t, 2);
        t += __shfl_xor_sync(0xffffffffu, t, 4);
        if (lane == 0) bc[1] = t;
    }
    __syncthreads();
    const float inv = 1.0f / (sqrtf(bc[1] * (1.0f / D)) + 1e-6f);

    float4 gg = *(const float4*)(g + tid * 4);
    float4 bb = *(const float4*)(b + tid * 4);
    float o0 = gg.x * dx * inv + bb.x;
    float o1 = gg.y * dy * inv + bb.y;
    float o2 = gg.z * dz * inv + bb.z;
    float o3 = gg.w * dw * inv + bb.w;
    const size_t base = (size_t)row * D + tid * 4;
    if (WF32) {
        float4 o4 = {o0, o1, o2, o3};
        *(float4*)(outf + base) = o4;
    }
    if (WSPLIT) {
        float vv[4] = {o0, o1, o2, o3};
        __nv_bfloat16 hs[4], ls[4];
#pragma unroll
        for (int i = 0; i < 4; i++) {
            hs[i] = __float2bfloat16_rn(vv[i]);
            ls[i] = __float2bfloat16_rn(vv[i] - __bfloat162float(hs[i]));
        }
        *(uint2*)(oh + base) = *(uint2*)hs;
        *(uint2*)(ol + base) = *(uint2*)ls;
    }
}

// ================= shared GEMM plumbing ======================================
__device__ __forceinline__ uint32_t swz(int row, int kb) {
    return (uint32_t)(row * 64 + ((kb ^ ((row >> 1) & 3)) << 4));
}

template<int ROWS>
__device__ __forceinline__ void load_tileT(
    const __nv_bfloat16* __restrict__ g, int ld, int row0, int k0, uint32_t sbase, int tid)
{
#pragma unroll
    for (int it = 0; it < ROWS / 64; it++) {
        int c = tid + (it << 8);
        int row = c >> 2, kb = c & 3;
        cpa16(sbase + swz(row, kb), g + (size_t)(row0 + row) * ld + k0 + kb * 8);
    }
}

#define WAIT_REM(rem) do { \
    if ((rem) >= 2)      asm volatile("cp.async.wait_group 2;" ::: "memory"); \
    else if ((rem) == 1) asm volatile("cp.async.wait_group 1;" ::: "memory"); \
    else                 asm volatile("cp.async.wait_group 0;" ::: "memory"); \
} while (0)

// ================= mma.sync GEMM (3-stage, occ 2): C = A[M,K] @ T[N,K]^T =====
template<int BN, int WF32, int WSPLIT, int RELU, int RESID>
__global__ __launch_bounds__(256, 2) void mma_gemm(
    const __nv_bfloat16* __restrict__ Ah, const __nv_bfloat16* __restrict__ Al,
    const __nv_bfloat16* __restrict__ Bh, const __nv_bfloat16* __restrict__ Bl,
    const float* __restrict__ bias, const float* __restrict__ res,
    float* __restrict__ Cf, __nv_bfloat16* __restrict__ Chi, __nv_bfloat16* __restrict__ Clo,
    int N, int K)
{
    constexpr int MT   = (BN == 128) ? 4 : 2;
    constexpr int BB   = BN * 64;
    constexpr int SA_H = 0, SA_L = 8192, SB_H = 16384;
    constexpr int SB_L = 16384 + BB;
    constexpr int SSZ  = 16384 + 2 * BB;

    extern __shared__ char smem[];
    const uint32_t sb = smem_u32(smem);
    const int tid = threadIdx.x, wid = tid >> 5, lane = tid & 31;
    const int warp_m = (BN == 128) ? (wid & 1) : (wid & 3);
    const int warp_n = (BN == 128) ? (wid >> 1) : (wid >> 2);
    const int brow = blockIdx.y * 128, bcol = blockIdx.x * BN;

    float acc[MT][4][4];
#pragma unroll
    for (int a = 0; a < MT; a++)
#pragma unroll
        for (int b = 0; b < 4; b++)
#pragma unroll
            for (int c = 0; c < 4; c++) acc[a][b][c] = 0.0f;

    const int nch = K >> 5;
    auto load_stage = [&](int ci, uint32_t st) {
        const int k0 = ci << 5;
        load_tileT<128>(Ah, K, brow, k0, st + SA_H, tid);
        load_tileT<128>(Al, K, brow, k0, st + SA_L, tid);
        load_tileT<BN>(Bh, K, bcol, k0, st + SB_H, tid);
        load_tileT<BN>(Bl, K, bcol, k0, st + SB_L, tid);
        CPA_COMMIT();
    };
    load_stage(0, sb);
    if (nch > 1) load_stage(1, sb + SSZ);

    const int tileA = lane >> 3;
    const int rinA  = (lane & 7) + ((tileA & 1) << 3);
    const int kbA   = tileA >> 1;
    const int i16   = lane & 15;
    const int rinB  = i16 & 7;
    const int kbB   = i16 >> 3;

    for (int i = 0; i < nch; i++) {
        if (i + 2 < nch) load_stage(i + 2, sb + ((i + 2) % 3) * SSZ);
        WAIT_REM(nch - 1 - i);
        __syncthreads();

        const uint32_t st = sb + (i % 3) * SSZ;
#pragma unroll
        for (int ks = 0; ks < 2; ks++) {
            uint32_t bh[4][2], bl[4][2];
#pragma unroll
            for (int nt = 0; nt < 4; nt++) {
                const int rowb = warp_n * 32 + nt * 8 + rinB;
                const uint32_t off = swz(rowb, (ks << 1) + kbB);
                ldm_x2(bh[nt][0], bh[nt][1], st + SB_H + off);
                ldm_x2(bl[nt][0], bl[nt][1], st + SB_L + off);
            }
#pragma unroll
            for (int mt = 0; mt < MT; mt++) {
                const int rowa = warp_m * (MT * 16) + mt * 16 + rinA;
                const uint32_t off = swz(rowa, (ks << 1) + kbA);
                uint32_t a0, a1, a2, a3, l0, l1, l2, l3;
                ldm_x4(a0, a1, a2, a3, st + SA_H + off);
                ldm_x4(l0, l1, l2, l3, st + SA_L + off);
#pragma unroll
                for (int nt = 0; nt < 4; nt++) {
                    mma_bf16(acc[mt][nt], a0, a1, a2, a3, bh[nt][0], bh[nt][1]);
                    mma_bf16(acc[mt][nt], a0, a1, a2, a3, bl[nt][0], bl[nt][1]);
                    mma_bf16(acc[mt][nt], l0, l1, l2, l3, bh[nt][0], bh[nt][1]);
                }
            }
        }
        __syncthreads();
    }

    const int g4 = lane >> 2, t4 = lane & 3;
#pragma unroll
    for (int mt = 0; mt < MT; mt++) {
#pragma unroll
        for (int half = 0; half < 2; half++) {
            const int row = brow + warp_m * (MT * 16) + mt * 16 + g4 + half * 8;
#pragma unroll
            for (int nt = 0; nt < 4; nt++) {
                const int col = bcol + warp_n * 32 + nt * 8 + t4 * 2;
                float v0 = acc[mt][nt][half * 2 + 0] + bias[col];
                float v1 = acc[mt][nt][half * 2 + 1] + bias[col + 1];
                if (RELU) { v0 = fmaxf(v0, 0.0f); v1 = fmaxf(v1, 0.0f); }
                const size_t o = (size_t)row * N + col;
                if (RESID) { v0 += res[o]; v1 += res[o + 1]; }
                if (WF32) {
                    float2 f2 = {v0, v1};
                    *(float2*)(Cf + o) = f2;
                }
                if (WSPLIT) {
                    __nv_bfloat16 h0 = __float2bfloat16_rn(v0);
                    __nv_bfloat16 h1 = __float2bfloat16_rn(v1);
                    __nv_bfloat16 q0 = __float2bfloat16_rn(v0 - __bfloat162float(h0));
                    __nv_bfloat16 q1 = __float2bfloat16_rn(v1 - __bfloat162float(h1));
                    __nv_bfloat162 hp = {h0, h1}, lp = {q0, q1};
                    *(__nv_bfloat162*)(Chi + o) = hp;
                    *(__nv_bfloat162*)(Clo + o) = lp;
                }
            }
        }
    }
}

#define GSMEM_128 (3 * 32768)
#define GSMEM_64  (3 * 24576)

// ================= score mma: S = (Q K^T)/8, causal ==========================
#define STG_A_H 0
#define STG_A_L 8192
#define STG_B_H 16384
#define STG_B_L 24576
#define STG_SZ  32768
#define SCORE_SMEM (2 * STG_SZ)

__global__ __launch_bounds__(256, 2) void score_mma(
    const __nv_bfloat16* __restrict__ qh, const __nv_bfloat16* __restrict__ ql,
    const __nv_bfloat16* __restrict__ kh, const __nv_bfloat16* __restrict__ kl,
    float* __restrict__ attn)
{
    const int brow = blockIdx.y * 128, bcol = blockIdx.x * 128;
    if (bcol >= brow + 128) return;
    const int h = blockIdx.z;
    const __nv_bfloat16* Ah = qh + h * DK;
    const __nv_bfloat16* Al = ql + h * DK;
    const __nv_bfloat16* Bh = kh + h * DK;
    const __nv_bfloat16* Bl = kl + h * DK;

    extern __shared__ char smem[];
    const uint32_t sb = smem_u32(smem);
    const int tid = threadIdx.x, wid = tid >> 5, lane = tid & 31;
    const int warp_m = wid & 1, warp_n = wid >> 1;

    float acc[4][4][4];
#pragma unroll
    for (int a = 0; a < 4; a++)
#pragma unroll
        for (int b = 0; b < 4; b++)
#pragma unroll
            for (int c = 0; c < 4; c++) acc[a][b][c] = 0.0f;

    load_tileT<128>(Ah, 3 * D, brow, 0, sb + STG_A_H, tid);
    load_tileT<128>(Al, 3 * D, brow, 0, sb + STG_A_L, tid);
    load_tileT<128>(Bh, 3 * D, bcol, 0, sb + STG_B_H, tid);
    load_tileT<128>(Bl, 3 * D, bcol, 0, sb + STG_B_L, tid);
    CPA_COMMIT();

    const int tileA = lane >> 3;
    const int rinA  = (lane & 7) + ((tileA & 1) << 3);
    const int kbA   = tileA >> 1;
    const int i16   = lane & 15;
    const int rinB  = i16 & 7;
    const int kbB   = i16 >> 3;

    for (int i = 0; i < 2; i++) {
        if (i == 0) {
            const uint32_t st = sb + STG_SZ;
            load_tileT<128>(Ah, 3 * D, brow, 32, st + STG_A_H, tid);
            load_tileT<128>(Al, 3 * D, brow, 32, st + STG_A_L, tid);
            load_tileT<128>(Bh, 3 * D, bcol, 32, st + STG_B_H, tid);
            load_tileT<128>(Bl, 3 * D, bcol, 32, st + STG_B_L, tid);
            CPA_COMMIT();
            asm volatile("cp.async.wait_group 1;" ::: "memory");
        } else {
            asm volatile("cp.async.wait_group 0;" ::: "memory");
        }
        __syncthreads();

        const uint32_t st = sb + (i & 1) * STG_SZ;
#pragma unroll
        for (int ks = 0; ks < 2; ks++) {
            uint32_t bh[4][2], bl[4][2];
#pragma unroll
            for (int nt = 0; nt < 4; nt++) {
                const int rowb = warp_n * 32 + nt * 8 + rinB;
                const uint32_t off = swz(rowb, (ks << 1) + kbB);
                ldm_x2(bh[nt][0], bh[nt][1], st + STG_B_H + off);
                ldm_x2(bl[nt][0], bl[nt][1], st + STG_B_L + off);
            }
#pragma unroll
            for (int mt = 0; mt < 4; mt++) {
                const int rowa = warp_m * 64 + mt * 16 + rinA;
                const uint32_t off = swz(rowa, (ks << 1) + kbA);
                uint32_t a0, a1, a2, a3, l0, l1, l2, l3;
                ldm_x4(a0, a1, a2, a3, st + STG_A_H + off);
                ldm_x4(l0, l1, l2, l3, st + STG_A_L + off);
#pragma unroll
                for (int nt = 0; nt < 4; nt++) {
                    mma_bf16(acc[mt][nt], a0, a1, a2, a3, bh[nt][0], bh[nt][1]);
                    mma_bf16(acc[mt][nt], a0, a1, a2, a3, bl[nt][0], bl[nt][1]);
                    mma_bf16(acc[mt][nt], l0, l1, l2, l3, bh[nt][0], bh[nt][1]);
                }
            }
        }
        __syncthreads();
    }

    const int g4 = lane >> 2, t4 = lane & 3;
#pragma unroll
    for (int mt = 0; mt < 4; mt++) {
#pragma unroll
        for (int half = 0; half < 2; half++) {
            const int row = brow + warp_m * 64 + mt * 16 + g4 + half * 8;
            float* arow = attn + ((size_t)h * SQ + row) * SQ;
#pragma unroll
            for (int nt = 0; nt < 4; nt++) {
                const int col = bcol + warp_n * 32 + nt * 8 + t4 * 2;
                if (col <= row)     arow[col]     = acc[mt][nt][half * 2 + 0] * 0.125f;
                if (col + 1 <= row) arow[col + 1] = acc[mt][nt][half * 2 + 1] * 0.125f;
            }
        }
    }
}

// ================= softmax (warp-shuffle, vectorized fills) ==================
__global__ __launch_bounds__(256) void softmax_kernel(
    float* __restrict__ attn,
    __nv_bfloat16* __restrict__ ah, __nv_bfloat16* __restrict__ al)
{
    __shared__ float p[SQ];
    __shared__ float red[8];
    __shared__ float bc[2];
    const int i   = blockIdx.x;
    const int h   = blockIdx.y;
    const int tid = threadIdx.x;
    const int lane = tid & 31, warp = tid >> 5;
    const size_t rb = ((size_t)h * SQ + i) * SQ;
    float* row = attn + rb;

    float m = -INFINITY;
    for (int j = tid; j <= i; j += 256) { float s = row[j]; p[j] = s; m = fmaxf(m, s); }
    m = wred_max(m);
    if (lane == 0) red[warp] = m;
    __syncthreads();
    if (warp == 0) {
        float t = red[lane & 7];
        t = fmaxf(t, __shfl_xor_sync(0xffffffffu, t, 1));
        t = fmaxf(t, __shfl_xor_sync(0xffffffffu, t, 2));
        t = fmaxf(t, __shfl_xor_sync(0xffffffffu, t, 4));
        if (lane == 0) bc[0] = t;
    }
    __syncthreads();
    const float mx = bc[0];

    float sum = 0.0f;
    for (int j = tid; j <= i; j += 256) { float e = __expf(p[j] - mx); p[j] = e; sum += e; }
    sum = wred_sum(sum);
    __syncthreads();
    if (lane == 0) red[warp] = sum;
    __syncthreads();
    if (warp == 0) {
        float t = red[lane & 7];
        t += __shfl_xor_sync(0xffffffffu, t, 1);
        t += __shfl_xor_sync(0xffffffffu, t, 2);
        t += __shfl_xor_sync(0xffffffffu, t, 4);
        if (lane == 0) bc[1] = t;
    }
    __syncthreads();
    const float inv = 1.0f / bc[1];

    const int lim = ((i >> 7) + 1) << 7;
    for (int j = tid; j <= i; j += 256) {
        float w = p[j] * inv;
        row[j] = w;
        __nv_bfloat16 hh = __float2bfloat16_rn(w);
        ah[rb + j] = hh;
        al[rb + j] = __float2bfloat16_rn(w - __bfloat162float(hh));
    }

    // vectorized zero fills above the diagonal
    const int zs = i + 1;
    const int za = (zs + 3) & ~3;
    if (tid < za - zs && zs + tid < SQ) row[zs + tid] = 0.0f;
    const float4 zf4 = {0.0f, 0.0f, 0.0f, 0.0f};
    for (int j = za + tid * 4; j < SQ; j += 1024) *(float4*)(row + j) = zf4;
    const __nv_bfloat16 z = __float2bfloat16_rn(0.0f);
    if (tid < za - zs && zs + tid < lim) { ah[rb + zs + tid] = z; al[rb + zs + tid] = z; }
    const uint2 zu2 = {0u, 0u};
    for (int j = za + tid * 4; j < lim; j += 1024) {
        *(uint2*)(ah + rb + j) = zu2;
        *(uint2*)(al + rb + j) = zu2;
    }
}

// ================= AV mma (3-stage, occ 2): ctx = P @ V ======================
#define AV_A_H 0
#define AV_A_L 8192
#define AV_B_H 16384
#define AV_B_L 20480
#define AV_STG 24576
#define AV_SMEM (3 * AV_STG)

__global__ __launch_bounds__(256, 2) void av_mma(
    const __nv_bfloat16* __restrict__ ah, const __nv_bfloat16* __restrict__ al,
    const __nv_bfloat16* __restrict__ vh, const __nv_bfloat16* __restrict__ vl,
    __nv_bfloat16* __restrict__ ch, __nv_bfloat16* __restrict__ cl)
{
    const int brow = blockIdx.x * 128;
    const int h    = blockIdx.y;
    const __nv_bfloat16* Ah = ah + (size_t)h * SQ * SQ;
    const __nv_bfloat16* Al = al + (size_t)h * SQ * SQ;
    const __nv_bfloat16* Vh = vh + 2 * D + h * DK;
    const __nv_bfloat16* Vl = vl + 2 * D + h * DK;

    extern __shared__ char smem[];
    const uint32_t sb = smem_u32(smem);
    const int tid = threadIdx.x, wid = tid >> 5, lane = tid & 31;
    const int warp_m = wid & 3;
    const int warp_n = wid >> 2;

    float acc[2][4][4];
#pragma unroll
    for (int a = 0; a < 2; a++)
#pragma unroll
        for (int b = 0; b < 4; b++)
#pragma unroll
            for (int c = 0; c < 4; c++) acc[a][b][c] = 0.0f;

    auto load_b = [&](const __nv_bfloat16* V, int k0, uint32_t sbase) {
        int r = tid >> 3, g = tid & 7;
        cpa16(sbase + (uint32_t)(r * 128 + ((g ^ (r & 7)) << 4)),
              V + (size_t)(k0 + r) * (3 * D) + g * 8);
    };
    auto load_stage = [&](int ci, uint32_t st) {
        const int k0 = ci << 5;
        load_tileT<128>(Ah, SQ, brow, k0, st + AV_A_H, tid);
        load_tileT<128>(Al, SQ, brow, k0, st + AV_A_L, tid);
        load_b(Vh, k0, st + AV_B_H);
        load_b(Vl, k0, st + AV_B_L);
        CPA_COMMIT();
    };

    const int nch = (brow >> 5) + 4;
    load_stage(0, sb);
    if (nch > 1) load_stage(1, sb + AV_STG);

    const int tileA = lane >> 3;
    const int rinA  = (lane & 7) + ((tileA & 1) << 3);
    const int kbA   = tileA >> 1;
    const int i16   = lane & 15;

    for (int i = 0; i < nch; i++) {
        if (i + 2 < nch) load_stage(i + 2, sb + ((i + 2) % 3) * AV_STG);
        WAIT_REM(nch - 1 - i);
        __syncthreads();

        const uint32_t st = sb + (i % 3) * AV_STG;
#pragma unroll
        for (int ks = 0; ks < 2; ks++) {
            uint32_t bh[4][2], bl[4][2];
#pragma unroll
            for (int nt = 0; nt < 4; nt++) {
                const int krow = ks * 16 + i16;
                const int gB = warp_n * 4 + nt;
                const uint32_t off = (uint32_t)(krow * 128 + ((gB ^ (krow & 7)) << 4));
                ldm_x2t(bh[nt][0], bh[nt][1], st + AV_B_H + off);
                ldm_x2t(bl[nt][0], bl[nt][1], st + AV_B_L + off);
            }
#pragma unroll
            for (int mt = 0; mt < 2; mt++) {
                const int rowa = warp_m * 32 + mt * 16 + rinA;
                const uint32_t off = swz(rowa, (ks << 1) + kbA);
                uint32_t a0, a1, a2, a3, l0, l1, l2, l3;
                ldm_x4(a0, a1, a2, a3, st + AV_A_H + off);
                ldm_x4(l0, l1, l2, l3, st + AV_A_L + off);
#pragma unroll
                for (int nt = 0; nt < 4; nt++) {
                    mma_bf16(acc[mt][nt], a0, a1, a2, a3, bh[nt][0], bh[nt][1]);
                    mma_bf16(acc[mt][nt], a0, a1, a2, a3, bl[nt][0], bl[nt][1]);
                    mma_bf16(acc[mt][nt], l0, l1, l2, l3, bh[nt][0], bh[nt][1]);
                }
            }
        }
        __syncthreads();
    }

    const int g4 = lane >> 2, t4 = lane & 3;
#pragma unroll
    for (int mt = 0; mt < 2; mt++) {
#pragma unroll
        for (int half = 0; half < 2; half++) {
            const int row = brow + warp_m * 32 + mt * 16 + g4 + half * 8;
#pragma unroll
            for (int nt = 0; nt < 4; nt++) {
                const int col = h * DK + warp_n * 32 + nt * 8 + t4 * 2;
                float v0 = acc[mt][nt][half * 2 + 0];
                float v1 = acc[mt][nt][half * 2 + 1];
                const size_t o = (size_t)row * D + col;
                __nv_bfloat16 h0 = __float2bfloat16_rn(v0);
                __nv_bfloat16 h1 = __float2bfloat16_rn(v1);
                __nv_bfloat16 q0 = __float2bfloat16_rn(v0 - __bfloat162float(h0));
                __nv_bfloat16 q1 = __float2bfloat16_rn(v1 - __bfloat162float(h1));
                __nv_bfloat162 hp = {h0, h1}, lp = {q0, q1};
                *(__nv_bfloat162*)(ch + o) = hp;
                *(__nv_bfloat162*)(cl + o) = lp;
            }
        }
    }
}

// ================= host driver =================
struct Scratch {
    __nv_bfloat16 *nxh, *nxl, *hh, *hl, *qkvh, *qkvl, *ctxh, *ctxl, *mhah, *mhal, *n2h, *n2l, *ff1h, *ff1l;
    __nv_bfloat16 *attnh, *attnl;
    __nv_bfloat16 *winth, *wintl, *wqkvth, *wqkvtl, *woth, *wotl, *w2th, *w2tl, *wf1th, *wf1tl, *wf2th, *wf2tl;
    float *p1, *n2, *attn, *bqkv;
};

static Scratch get_scratch() {
    static Scratch s = [] {
        Scratch t;
        void* p;
        cudaGetSymbolAddress(&p, g_nx_h);   t.nxh = (__nv_bfloat16*)p;
        cudaGetSymbolAddress(&p, g_nx_l);   t.nxl = (__nv_bfloat16*)p;
        cudaGetSymbolAddress(&p, g_h_h);    t.hh  = (__nv_bfloat16*)p;
        cudaGetSymbolAddress(&p, g_h_l);    t.hl  = (__nv_bfloat16*)p;
        cudaGetSymbolAddress(&p, g_qkv_h);  t.qkvh = (__nv_bfloat16*)p;
        cudaGetSymbolAddress(&p, g_qkv_l);  t.qkvl = (__nv_bfloat16*)p;
        cudaGetSymbolAddress(&p, g_ctx_h);  t.ctxh = (__nv_bfloat16*)p;
        cudaGetSymbolAddress(&p, g_ctx_l);  t.ctxl = (__nv_bfloat16*)p;
        cudaGetSymbolAddress(&p, g_mha_h);  t.mhah = (__nv_bfloat16*)p;
        cudaGetSymbolAddress(&p, g_mha_l);  t.mhal = (__nv_bfloat16*)p;
        cudaGetSymbolAddress(&p, g_n2_h);   t.n2h = (__nv_bfloat16*)p;
        cudaGetSymbolAddress(&p, g_n2_l);   t.n2l = (__nv_bfloat16*)p;
        cudaGetSymbolAddress(&p, g_ff1_h);  t.ff1h = (__nv_bfloat16*)p;
        cudaGetSymbolAddress(&p, g_ff1_l);  t.ff1l = (__nv_bfloat16*)p;
        cudaGetSymbolAddress(&p, g_attn_h); t.attnh = (__nv_bfloat16*)p;
        cudaGetSymbolAddress(&p, g_attn_l); t.attnl = (__nv_bfloat16*)p;
        cudaGetSymbolAddress(&p, g_wint_h); t.winth = (__nv_bfloat16*)p;
        cudaGetSymbolAddress(&p, g_wint_l); t.wintl = (__nv_bfloat16*)p;
        cudaGetSymbolAddress(&p, g_wqkvt_h); t.wqkvth = (__nv_bfloat16*)p;
        cudaGetSymbolAddress(&p, g_wqkvt_l); t.wqkvtl = (__nv_bfloat16*)p;
        cudaGetSymbolAddress(&p, g_wot_h);  t.woth = (__nv_bfloat16*)p;
        cudaGetSymbolAddress(&p, g_wot_l);  t.wotl = (__nv_bfloat16*)p;
        cudaGetSymbolAddress(&p, g_w2t_h);  t.w2th = (__nv_bfloat16*)p;
        cudaGetSymbolAddress(&p, g_w2t_l);  t.w2tl = (__nv_bfloat16*)p;
        cudaGetSymbolAddress(&p, g_wf1t_h); t.wf1th = (__nv_bfloat16*)p;
        cudaGetSymbolAddress(&p, g_wf1t_l); t.wf1tl = (__nv_bfloat16*)p;
        cudaGetSymbolAddress(&p, g_wf2t_h); t.wf2th = (__nv_bfloat16*)p;
        cudaGetSymbolAddress(&p, g_wf2t_l); t.wf2tl = (__nv_bfloat16*)p;
        cudaGetSymbolAddress(&p, g_p1);     t.p1  = (float*)p;
        cudaGetSymbolAddress(&p, g_n2);     t.n2  = (float*)p;
        cudaGetSymbolAddress(&p, g_attn_scratch); t.attn = (float*)p;
        cudaGetSymbolAddress(&p, g_bqkv);   t.bqkv = (float*)p;
        cudaFuncSetAttribute((const void*)mma_gemm<64,0,1,0,0>,  cudaFuncAttributeMaxDynamicSharedMemorySize, GSMEM_64);
        cudaFuncSetAttribute((const void*)mma_gemm<64,1,0,0,1>,  cudaFuncAttributeMaxDynamicSharedMemorySize, GSMEM_64);
        cudaFuncSetAttribute((const void*)mma_gemm<128,0,1,0,0>, cudaFuncAttributeMaxDynamicSharedMemorySize, GSMEM_128);
        cudaFuncSetAttribute((const void*)mma_gemm<128,0,1,1,0>, cudaFuncAttributeMaxDynamicSharedMemorySize, GSMEM_128);
        cudaFuncSetAttribute((const void*)score_mma, cudaFuncAttributeMaxDynamicSharedMemorySize, SCORE_SMEM);
        cudaFuncSetAttribute((const void*)av_mma,    cudaFuncAttributeMaxDynamicSharedMemorySize, AV_SMEM);
        return t;
    }();
    return s;
}

extern "C" void kernel_launch(void* const* d_in, const int* in_sizes, int n_in,
                              void* d_out, int out_size)
{
    const float* x     = (const float*)d_in[0];
    const float* g1    = (const float*)d_in[1];
    const float* beta1 = (const float*)d_in[2];
    const float* W_in  = (const float*)d_in[3];
    const float* b_in  = (const float*)d_in[4];
    const float* Wq    = (const float*)d_in[5];
    const float* bq    = (const float*)d_in[6];
    const float* Wk    = (const float*)d_in[7];
    const float* bk    = (const float*)d_in[8];
    const float* Wv    = (const float*)d_in[9];
    const float* bv    = (const float*)d_in[10];
    const float* Wo    = (const float*)d_in[11];
    const float* bo    = (const float*)d_in[12];
    const float* W2    = (const float*)d_in[13];
    const float* b2    = (const float*)d_in[14];
    const float* g2    = (const float*)d_in[15];
    const float* beta2 = (const float*)d_in[16];
    const float* Wf1   = (const float*)d_in[17];
    const float* bf1   = (const float*)d_in[18];
    const float* Wf2   = (const float*)d_in[19];
    const float* bf2   = (const float*)d_in[20];

    Scratch s = get_scratch();

    float* out  = (float*)d_out;
    const long long full = (long long)SQ * D + (long long)NH * SQ * SQ;
    float* attn = ((long long)out_size >= full) ? (out + (size_t)SQ * D) : s.attn;

    dim3 blk(256);
    dim3 wblk(32, 8);

    // #1/#2: batched weight prep
    wprep_dd<<<dim3(32, 32, 6), wblk>>>(
        W_in, Wq, Wk, Wv, Wo, W2, bq, bk, bv,
        s.winth, s.wintl, s.wqkvth, s.wqkvtl, s.woth, s.wotl, s.w2th, s.w2tl, s.bqkv);
    wprep_ff<<<dim3(128, 32, 2), wblk>>>(Wf1, Wf2, s.wf1th, s.wf1tl, s.wf2th, s.wf2tl);

    // #3: LN1 -> split
    ln_kernel<0,1><<<SQ, blk>>>(x, g1, beta1, nullptr, s.nxh, s.nxl);
    // #4: h = nx @ W_in + b_in (BN=64, grid 256)
    mma_gemm<64,0,1,0,0><<<dim3(D/64, SQ/128), 256, GSMEM_64>>>(
        s.nxh, s.nxl, s.winth, s.wintl, b_in, nullptr, nullptr, s.hh, s.hl, D, D);
    // #5: qkv (BN=128, grid 384)
    mma_gemm<128,0,1,0,0><<<dim3(3*D/128, SQ/128), 256, GSMEM_128>>>(
        s.hh, s.hl, s.wqkvth, s.wqkvtl, s.bqkv, nullptr, nullptr, s.qkvh, s.qkvl, 3*D, D);
    // #6: scores  [ncu -s 5 captures this]
    score_mma<<<dim3(SQ/128, SQ/128, NH), 256, SCORE_SMEM>>>(
        s.qkvh, s.qkvl, s.qkvh + D, s.qkvl + D, attn);
    // #7: softmax
    softmax_kernel<<<dim3(SQ, NH), blk>>>(attn, s.attnh, s.attnl);
    // #8: AV
    av_mma<<<dim3(SQ/128, NH), 256, AV_SMEM>>>(
        s.attnh, s.attnl, s.qkvh, s.qkvl, s.ctxh, s.ctxl);
    // #9: mha = ctx @ Wo + bo (BN=64)
    mma_gemm<64,0,1,0,0><<<dim3(D/64, SQ/128), 256, GSMEM_64>>>(
        s.ctxh, s.ctxl, s.woth, s.wotl, bo, nullptr, nullptr, s.mhah, s.mhal, D, D);
    // #10: p1 = x + mha @ W2 + b2 (BN=64)
    mma_gemm<64,1,0,0,1><<<dim3(D/64, SQ/128), 256, GSMEM_64>>>(
        s.mhah, s.mhal, s.w2th, s.w2tl, b2, x, s.p1, nullptr, nullptr, D, D);
    // #11: LN2
    ln_kernel<1,1><<<SQ, blk>>>(s.p1, g2, beta2, s.n2, s.n2h, s.n2l);
    // #12: ff1 = relu(n2 @ Wf1 + bf1) (BN=128, grid 512)
    mma_gemm<128,0,1,1,0><<<dim3(DFF/128, SQ/128), 256, GSMEM_128>>>(
        s.n2h, s.n2l, s.wf1th, s.wf1tl, bf1, nullptr, nullptr, s.ff1h, s.ff1l, DFF, D);
    // #13: out = n2 + ff1 @ Wf2 + bf2 (BN=64, K=4096)
    mma_gemm<64,1,0,0,1><<<dim3(D/64, SQ/128), 256, GSMEM_64>>>(
        s.ff1h, s.ff1l, s.wf2th, s.wf2tl, bf2, s.n2, out, nullptr, nullptr, D, DFF);
}